// round 1
// baseline (speedup 1.0000x reference)
#include <cuda_runtime.h>
#include <cuda_bf16.h>
#include <cstdint>

// Problem constants
#define SEQ   4096
#define DK    128
#define PLANE (SEQ * DK)       // 524288 elems per (b,h) plane
#define PLANE4 (PLANE / 4)     // 131072 float4s per plane (power of 2)

// Scratch: diagonal of R, stored [s][d] to match x's innermost layout.
// 2 MB — fits L2, reused 128x by the scale kernel.
__device__ float4 g_diag4[PLANE4];

// Kernel 1: extract R[d,d,s] -> g_diag[s*128 + d].
// R layout is (d_k, d_k, seq): index (d*DK + d)*SEQ + s = d*129*SEQ + s.
// Writes are fully coalesced (consecutive d for fixed s); reads hit 32 distinct
// sectors per warp but total traffic is tiny (~16 MB L2-side worst case).
__global__ void extract_diag_kernel(const float* __restrict__ R) {
    unsigned j = blockIdx.x * blockDim.x + threadIdx.x;  // 0 .. PLANE-1
    if (j >= PLANE) return;
    unsigned s = j >> 7;      // j / 128
    unsigned d = j & 127;     // j % 128
    float v = R[(size_t)d * (DK + 1) * SEQ + s];
    reinterpret_cast<float*>(g_diag4)[(size_t)s * DK + d] = v;
}

// Kernel 2: out = x * diag (broadcast over batch*heads).
// Pure streaming: 128-bit loads/stores, diag served from L2.
__global__ void scale_kernel(const float4* __restrict__ x,
                             float4* __restrict__ out,
                             unsigned n4) {
    unsigned i = blockIdx.x * blockDim.x + threadIdx.x;
    if (i >= n4) return;
    float4 xv = x[i];
    float4 dv = g_diag4[i & (PLANE4 - 1)];
    xv.x *= dv.x;
    xv.y *= dv.y;
    xv.z *= dv.z;
    xv.w *= dv.w;
    out[i] = xv;
}

extern "C" void kernel_launch(void* const* d_in, const int* in_sizes, int n_in,
                              void* d_out, int out_size) {
    const float* x = (const float*)d_in[0];
    // d_in[1] = token_positions (unused by the reference semantics)
    const float* R = (const float*)d_in[2];
    float* out = (float*)d_out;

    // Kernel 1: diag extraction (524288 threads)
    {
        const int T = 256;
        const int B = (PLANE + T - 1) / T;  // 2048
        extract_diag_kernel<<<B, T>>>(R);
    }

    // Kernel 2: elementwise scale, float4 vectorized
    {
        unsigned n4 = (unsigned)out_size / 4;  // 16,777,216
        const int T = 256;
        const unsigned B = (n4 + T - 1) / T;   // 65536
        scale_kernel<<<B, T>>>((const float4*)x, (float4*)out, n4);
    }
}

// round 2
// speedup vs baseline: 1.0511x; 1.0511x over previous
#include <cuda_runtime.h>
#include <cuda_bf16.h>
#include <cstdint>

// Problem constants
#define SEQ    4096
#define DK     128
#define PLANE  (SEQ * DK)      // 524288 elems per (b,h) plane
#define PLANE4 (PLANE / 4)     // 131072 float4s per plane (power of 2)

// Scratch: diagonal of R, stored [s][d] to match x's innermost layout.
// 2 MB — stays L2-resident (streaming hints keep x/out from evicting it).
__device__ float4 g_diag4[PLANE4];

// Kernel 1: extract R[d,d,s] -> g_diag[s*128 + d] via smem tile transpose.
// R diag element (d,s) lives at R[d*(DK+1)*SEQ + s] — contiguous in s per d.
// Read side: warp reads 32 consecutive s for one d (coalesced 128B).
// Write side: warp writes 32 consecutive d for one s (coalesced 128B).
__global__ void extract_diag_kernel(const float* __restrict__ R) {
    __shared__ float tile[32][33];          // +1 pad: conflict-free transpose
    const unsigned d0 = blockIdx.x * 32;    // 4 tiles over d
    const unsigned s0 = blockIdx.y * 32;    // 128 tiles over s
    const unsigned tx = threadIdx.x;        // 0..31
    const unsigned ty = threadIdx.y;        // 0..7

    #pragma unroll
    for (int r = 0; r < 4; r++) {
        unsigned dd = ty + r * 8;           // row within tile = d offset
        tile[dd][tx] = R[(size_t)(d0 + dd) * (DK + 1) * SEQ + (s0 + tx)];
    }
    __syncthreads();
    float* diag = reinterpret_cast<float*>(g_diag4);
    #pragma unroll
    for (int r = 0; r < 4; r++) {
        unsigned ss = ty + r * 8;           // row within tile = s offset
        diag[(size_t)(s0 + ss) * DK + (d0 + tx)] = tile[tx][ss];
    }
}

// Kernel 2: out = x * diag (broadcast over 128 (b,h) planes).
// 4 float4s per thread, loads front-batched for MLP; streaming cache hints
// on x/out so the diag stays hot in L2.
__global__ void __launch_bounds__(256) scale_kernel(
        const float4* __restrict__ x,
        float4* __restrict__ out,
        unsigned n4) {
    unsigned base = blockIdx.x * (blockDim.x * 4) + threadIdx.x;

    float4 xv[4], dv[4];
    #pragma unroll
    for (int k = 0; k < 4; k++) {
        unsigned i = base + k * 256;
        xv[k] = __ldcs(&x[i]);                       // evict-first: pure stream
        dv[k] = g_diag4[i & (PLANE4 - 1)];           // L2-resident broadcast
    }
    #pragma unroll
    for (int k = 0; k < 4; k++) {
        unsigned i = base + k * 256;
        float4 r;
        r.x = xv[k].x * dv[k].x;
        r.y = xv[k].y * dv[k].y;
        r.z = xv[k].z * dv[k].z;
        r.w = xv[k].w * dv[k].w;
        __stcs(&out[i], r);                          // streaming store
    }
    (void)n4;  // n4 = 16M is exactly divisible by 1024-per-block; no tail
}

extern "C" void kernel_launch(void* const* d_in, const int* in_sizes, int n_in,
                              void* d_out, int out_size) {
    const float* x = (const float*)d_in[0];
    // d_in[1] = token_positions (unused by the reference semantics)
    const float* R = (const float*)d_in[2];
    float* out = (float*)d_out;

    // Kernel 1: coalesced diag extraction (512 blocks x 256 threads)
    {
        dim3 grid(DK / 32, SEQ / 32);   // (4, 128)
        dim3 block(32, 8);
        extract_diag_kernel<<<grid, block>>>(R);
    }

    // Kernel 2: elementwise scale, 4x unrolled float4
    {
        unsigned n4 = (unsigned)out_size / 4;        // 16,777,216
        unsigned B = n4 / (256 * 4);                 // 16384 blocks, exact
        scale_kernel<<<B, 256>>>((const float4*)x, (float4*)out, n4);
    }
}

// round 3
// speedup vs baseline: 1.0662x; 1.0143x over previous
#include <cuda_runtime.h>
#include <cuda_bf16.h>
#include <cstdint>

// Problem constants
#define SEQ    4096
#define DK     128
#define PLANE  (SEQ * DK)      // 524288 elems per (b,h) plane
#define PLANE4 (PLANE / 4)     // 131072 float4s per plane
#define PPB    2               // planes per block (diag reuse + MLP depth)

// Fused kernel: out[...,s,d] = R[d,d,s] * x[...,s,d]
// One block = one 32-seq x 128-dim tile, applied to PPB planes.
// Diag slice is read straight from R (coalesced, L2-cached across planes)
// into smem, then broadcast to the streaming multiply.
__global__ void __launch_bounds__(256) rope_diag_kernel(
        const float* __restrict__ R,
        const float4* __restrict__ x,
        float4* __restrict__ out) {
    // Padded to 132 floats/row: 16B-aligned rows -> conflict-free LDS.128
    __shared__ float diag[32][132];

    const unsigned s0     = blockIdx.x * 32;        // 128 s-tiles
    const unsigned plane0 = blockIdx.y * PPB;       // 64 plane-pairs
    const unsigned tid    = threadIdx.x;
    const unsigned warp   = tid >> 5;
    const unsigned lane   = tid & 31;

    // Load diag slice: R[d,d,s] at R[d*(DK+1)*SEQ + s], contiguous in s.
    // Warp w handles d = w, w+8, ... : each row is a coalesced 128B read.
    #pragma unroll
    for (int r = 0; r < 16; r++) {
        unsigned d = warp + r * 8;
        diag[lane][d] = __ldg(&R[(size_t)d * ((DK + 1) * SEQ) + s0 + lane]);
    }
    __syncthreads();

    const unsigned tileBase = blockIdx.x * 1024;    // float4 offset in plane

    // Front-batch all 8 global loads (2 planes x 4 float4s) for MLP depth.
    float4 xv[PPB][4];
    #pragma unroll
    for (int p = 0; p < PPB; p++) {
        const float4* xp = x + (size_t)(plane0 + p) * PLANE4 + tileBase;
        #pragma unroll
        for (int k = 0; k < 4; k++)
            xv[p][k] = __ldcs(&xp[k * 256 + tid]);
    }

    #pragma unroll
    for (int k = 0; k < 4; k++) {
        unsigned idx = k * 256 + tid;               // 0..1023 within tile
        unsigned s   = idx >> 5;                    // 0..31
        unsigned d4  = (idx & 31) * 4;              // 0,4,...,124
        float4 dv = *reinterpret_cast<const float4*>(&diag[s][d4]);
        #pragma unroll
        for (int p = 0; p < PPB; p++) {
            float4 r;
            r.x = xv[p][k].x * dv.x;
            r.y = xv[p][k].y * dv.y;
            r.z = xv[p][k].z * dv.z;
            r.w = xv[p][k].w * dv.w;
            __stcs(&out[(size_t)(plane0 + p) * PLANE4 + tileBase + idx], r);
        }
    }
}

extern "C" void kernel_launch(void* const* d_in, const int* in_sizes, int n_in,
                              void* d_out, int out_size) {
    const float* x = (const float*)d_in[0];
    // d_in[1] = token_positions (unused by the reference semantics)
    const float* R = (const float*)d_in[2];
    float* out = (float*)d_out;

    dim3 grid(SEQ / 32, 128 / PPB);   // (128, 64) = 8192 blocks
    rope_diag_kernel<<<grid, 256>>>(R, (const float4*)x, (float4*)out);
    (void)in_sizes; (void)n_in; (void)out_size;
}